// round 13
// baseline (speedup 1.0000x reference)
#include <cuda_runtime.h>
#include <cuda_fp16.h>
#include <cstdint>

#define NMAX 100000
#define EMAX 800000

// -------- scratch (static __device__, no allocation) --------
__device__ __half g_Qh[NMAX * 128];
__device__ __half g_KVh[NMAX * 256];   // interleaved: [k0..3 v0..3 k4..7 v4..7 ...]
__device__ int   g_perm[NMAX];
__device__ int   g_cnt[3];
__device__ int   g_cnt2[3];
__device__ int   g_total;
__device__ int   g_wq;                 // dynamic work cursor for attn
// CSR by destination
__device__ int   g_deg[NMAX];
__device__ __align__(8) int2 g_offdeg[NMAX];  // {offset, degree} for attn
__device__ int   g_cur2[NMAX];
__device__ __align__(8) int2 g_epk[EMAX];   // {src|comb<<17|et<<22, phi_bits}
// pre-packed fp16 weights in mma.sync B-fragment order
__device__ __align__(16) uint4 g_Bpk[3][3][2048];
// precomputed rel/sign tables: [et*3+sidx][128]
__device__ __align__(16) float g_tqk[3072];
__device__ __align__(16) float g_tv[3072];

// ---------------- helpers ----------------
__device__ __forceinline__ uint32_t pack_half(float a, float b) {
    __half2 t = __floats2half2_rn(a, b);
    return *(uint32_t*)&t;
}

__device__ __forceinline__ void mma16816h(float* c,
    uint32_t a0, uint32_t a1, uint32_t a2, uint32_t a3,
    uint32_t b0, uint32_t b1)
{
    asm volatile(
        "mma.sync.aligned.m16n8k16.row.col.f32.f16.f16.f32 "
        "{%0,%1,%2,%3}, {%4,%5,%6,%7}, {%8,%9}, {%0,%1,%2,%3};"
        : "+f"(c[0]), "+f"(c[1]), "+f"(c[2]), "+f"(c[3])
        : "r"(a0), "r"(a1), "r"(a2), "r"(a3), "r"(b0), "r"(b1));
}

__device__ __forceinline__ uint32_t s2u(const void* p) {
    uint32_t a;
    asm("{ .reg .u64 t; cvta.to.shared.u64 t, %1; cvt.u32.u64 %0, t; }" : "=r"(a) : "l"(p));
    return a;
}

__device__ __forceinline__ void cp16(uint32_t s, const void* g) {
    asm volatile("cp.async.cg.shared.global [%0], [%1], 16;" :: "r"(s), "l"(g));
}

// ---------------- K1: fused histograms + weight pack + tables ----------------
__global__ void k_histpack(const int* __restrict__ ntype, const int* __restrict__ ei,
                           const float* __restrict__ Wq, const float* __restrict__ Wk,
                           const float* __restrict__ Wv,
                           const float* __restrict__ rq, const float* __restrict__ rk,
                           const float* __restrict__ rv,
                           const float* __restrict__ skf, const float* __restrict__ svf,
                           const float* __restrict__ skn, const float* __restrict__ svn,
                           int N, int E, int EB)
{
    int tid = threadIdx.x;
    if ((int)blockIdx.x < EB) {
        __shared__ int h[3];
        if (tid < 3) h[tid] = 0;
        __syncthreads();
        int i = blockIdx.x * blockDim.x + tid;
        if (i < N) atomicAdd(&h[ntype[i]], 1);
        if (i < E) atomicAdd(&g_deg[ei[E + i]], 1);
        __syncthreads();
        if (tid < 3 && h[tid]) atomicAdd(&g_cnt[tid], h[tid]);
        return;
    }

    // first pack block also resets counters consumed by k_off (launch-ordered)
    if ((int)blockIdx.x == EB) {
        if (tid == 0) g_total = 0;
        if (tid < 3) g_cnt2[tid] = 0;
    }

    int gid = (blockIdx.x - EB) * blockDim.x + tid;
    if (gid < 3072) {
        int c = gid >> 7, d = gid & 127;
        int et = c / 3, s = c - et * 3;
        float sk = (s < 2) ? skf[s * 128 + d] : skn[d];
        float sv = (s < 2) ? svf[s * 128 + d] : svn[d];
        g_tqk[gid] = rq[et * 128 + d] * rk[et * 128 + d] * sk;
        g_tv[gid]  = rv[et * 128 + d] * sv;
    }
    if (gid >= 3 * 3 * 2048) return;
    int t = gid / 6144;
    int m = (gid % 6144) / 2048;
    int w = gid % 2048;
    int kt = w >> 8;
    int np = (w >> 5) & 7;
    int lane = w & 31;

    const float* W = (m == 0 ? Wq : (m == 1 ? Wk : Wv)) + (size_t)t * 16384;
    int k0 = kt * 16 + (lane & 3) * 2;
    int n0 = (2 * np) * 8 + (lane >> 2);

    uint4 hi;
    uint32_t* hp = (uint32_t*)&hi;
    #pragma unroll
    for (int j = 0; j < 2; ++j) {
        int n = n0 + j * 8;
        #pragma unroll
        for (int g = 0; g < 2; ++g) {
            float v0 = W[(k0 + g * 8) * 128 + n];
            float v1 = W[(k0 + g * 8 + 1) * 128 + n];
            hp[j * 2 + g] = pack_half(v0, v1);
        }
    }
    g_Bpk[t][m][w] = hi;
}

// ---------------- K2: CSR offsets + type-scatter ----------------
__global__ void __launch_bounds__(256) k_off(const int* __restrict__ ntype, int N) {
    __shared__ int sws[8];
    __shared__ int sbase;
    __shared__ int h[3], tb[3];

    int tid = threadIdx.x;
    int lane = tid & 31, w = tid >> 5;
    int i = blockIdx.x * 256 + tid;
    int d = (i < N) ? g_deg[i] : 0;

    if (blockIdx.x == 0 && tid == 0) g_wq = 0;   // for k_attn (launch-ordered)

    int inc = d;
    #pragma unroll
    for (int o = 1; o < 32; o <<= 1) {
        int t = __shfl_up_sync(0xffffffffu, inc, o);
        if (lane >= o) inc += t;
    }
    if (lane == 31) sws[w] = inc;
    if (tid < 3) h[tid] = 0;
    __syncthreads();
    if (tid == 0) {
        int run = 0;
        #pragma unroll
        for (int k = 0; k < 8; ++k) { int t = sws[k]; sws[k] = run; run += t; }
        sbase = atomicAdd(&g_total, run);
    }
    __syncthreads();
    int ex = sbase + sws[w] + inc - d;
    if (i < N) {
        g_offdeg[i] = make_int2(ex, d);
        g_cur2[i] = ex;
    }

    int t = 0, r = 0;
    if (i < N) { t = ntype[i]; r = atomicAdd(&h[t], 1); }
    __syncthreads();
    if (tid < 3 && h[tid]) tb[tid] = atomicAdd(&g_cnt2[tid], h[tid]);
    __syncthreads();
    if (i < N) {
        int base = (t == 0) ? 0 : ((t == 1) ? g_cnt[0] : (g_cnt[0] + g_cnt[1]));
        g_perm[base + tb[t] + r] = i;
    }
}

// ---------------- K3: fused edge scatter + tensor-core QKV ----------------
// qkv: 512 threads, 16 warps as 4M x 4N tiles of 32x32. A in regs, dbuf B.
#define SM_B0 0
#define SM_B1 32768
#define SM_STAGE 65536
#define SM_META (65536 + 33792)
#define SM_TOTAL (SM_META + 1024)

__device__ __forceinline__ void copyB(uint32_t dst, const uint4* src, int tid) {
    #pragma unroll
    for (int i = tid; i < 2048; i += 512) cp16(dst + i * 16, src + i);
    asm volatile("cp.async.commit_group;");
}

__global__ void __launch_bounds__(512) k_qkv_es(
    const float* __restrict__ x, const int* __restrict__ ntype,
    const float* __restrict__ bq, const float* __restrict__ bk,
    const float* __restrict__ bv,
    const int* __restrict__ ei, const int* __restrict__ etype,
    const int* __restrict__ esign, const float* __restrict__ edist,
    const float* __restrict__ alphap, const float* __restrict__ taup,
    int N, int E, int EB)
{
    int tid = threadIdx.x;

    // ---- escatter blocks ----
    if ((int)blockIdx.x < EB) {
        int e = blockIdx.x * 512 + tid;
        if (e >= E) return;
        int dst = ei[E + e];
        int src = ei[e];
        int et = etype[e];
        int sg = esign[e];
        int sidx = (sg == -1) ? 0 : ((sg == 1) ? 1 : 2);
        float alpha = __ldg(alphap);
        float itau = 1.f / (__ldg(taup) + 1e-9f);
        float phi = alpha * __expf(-edist[e] * itau);
        int pos = atomicAdd(&g_cur2[dst], 1);
        int w = src | ((et * 3 + sidx) << 17) | (et << 22);
        g_epk[pos] = make_int2(w, __float_as_int(phi));
        return;
    }

    // ---- qkv blocks ----
    extern __shared__ __align__(16) unsigned char sm[];
    uint32_t smb = s2u(sm);
    float* raw = (float*)(sm + SM_STAGE);     // 64 rows x 132 floats
    int* sp = (int*)(sm + SM_META);
    int* st = sp + 128;

    int wid = tid >> 5;
    int lane = tid & 31;
    int mi = wid & 3;
    int ni = wid >> 2;

    int start = (blockIdx.x - EB) * 128;
    int count = N - start; if (count > 128) count = 128;

    if (tid < count) {
        int pn = g_perm[start + tid];
        sp[tid] = pn;
        st[tid] = ntype[pn];
    }
    __syncthreads();

    int tmin = st[0], tmax = st[count - 1];
    int niter = 3 * (tmax - tmin + 1);

    // prefetch first B while we stage A
    copyB(smb + SM_B0, g_Bpk[tmin][0], tid);

    // A fragments -> registers: warp covers rows mi*32..+32 (2 m-subtiles)
    uint4 a2[8][2];
    #pragma unroll
    for (int chunk = 0; chunk < 2; ++chunk) {
        for (int i = tid; i < 2048; i += 512) {
            int row = i >> 5, col = i & 31;
            int gr = chunk * 64 + row;
            float4 v = make_float4(0.f, 0.f, 0.f, 0.f);
            if (gr < count) v = *(const float4*)(x + (size_t)sp[gr] * 128 + col * 4);
            *(float4*)(raw + row * 132 + col * 4) = v;
        }
        __syncthreads();
        if ((mi >> 1) == chunk) {
            int q2 = (lane & 3) * 2;
            #pragma unroll
            for (int s = 0; s < 2; ++s) {
                int lr = (mi & 1) * 32 + s * 16 + (lane >> 2);
                #pragma unroll
                for (int kt = 0; kt < 8; ++kt) {
                    const float* b0 = raw + lr * 132 + kt * 16 + q2;
                    float2 f00 = *(const float2*)(b0);
                    float2 f10 = *(const float2*)(b0 + 8 * 132);
                    float2 f01 = *(const float2*)(b0 + 8);
                    float2 f11 = *(const float2*)(b0 + 8 * 132 + 8);
                    a2[kt][s].x = pack_half(f00.x, f00.y);
                    a2[kt][s].y = pack_half(f10.x, f10.y);
                    a2[kt][s].z = pack_half(f01.x, f01.y);
                    a2[kt][s].w = pack_half(f11.x, f11.y);
                }
            }
        }
        __syncthreads();
    }

    for (int it = 0; it < niter; ++it) {
        int t = tmin + it / 3;
        int m = it % 3;
        uint4* Bb = (uint4*)(sm + ((it & 1) ? SM_B1 : SM_B0));

        if (it + 1 < niter) {
            int t2 = tmin + (it + 1) / 3;
            int m2 = (it + 1) % 3;
            copyB(smb + ((it & 1) ? SM_B0 : SM_B1), g_Bpk[t2][m2], tid);
            asm volatile("cp.async.wait_group 1;" ::: "memory");
        } else {
            asm volatile("cp.async.wait_group 0;" ::: "memory");
        }
        __syncthreads();

        float acc[8][4];
        #pragma unroll
        for (int i = 0; i < 8; ++i)
            #pragma unroll
            for (int j = 0; j < 4; ++j) acc[i][j] = 0.f;

        #pragma unroll
        for (int kt = 0; kt < 8; ++kt) {
            uint4 b0 = Bb[(kt * 8 + 2 * ni) * 32 + lane];
            uint4 b1 = Bb[(kt * 8 + 2 * ni + 1) * 32 + lane];
            #pragma unroll
            for (int s = 0; s < 2; ++s) {
                uint4 ah = a2[kt][s];
                mma16816h(acc[s * 4 + 0], ah.x, ah.y, ah.z, ah.w, b0.x, b0.y);
                mma16816h(acc[s * 4 + 1], ah.x, ah.y, ah.z, ah.w, b0.z, b0.w);
                mma16816h(acc[s * 4 + 2], ah.x, ah.y, ah.z, ah.w, b1.x, b1.y);
                mma16816h(acc[s * 4 + 3], ah.x, ah.y, ah.z, ah.w, b1.z, b1.w);
            }
        }

        // ---- epilogue (fp16 outputs) ----
        const float* bias = (m == 0 ? bq : (m == 1 ? bk : bv)) + t * 128;
        int cbase = (lane & 3) * 2;
        int moff = (m == 2) ? 4 : 0;
        bool il = (m != 0);

        #pragma unroll
        for (int s = 0; s < 2; ++s) {
            int row0 = mi * 32 + s * 16 + (lane >> 2);
            int row1 = row0 + 8;
            bool v0ok = (row0 < count) && (st[row0] == t);
            bool v1ok = (row1 < count) && (st[row1] == t);
            __half* d0 = nullptr;
            __half* d1 = nullptr;
            if (il) {
                if (v0ok) d0 = g_KVh + (size_t)sp[row0] * 256 + moff;
                if (v1ok) d1 = g_KVh + (size_t)sp[row1] * 256 + moff;
            } else {
                if (v0ok) d0 = g_Qh + (size_t)sp[row0] * 128;
                if (v1ok) d1 = g_Qh + (size_t)sp[row1] * 128;
            }
            #pragma unroll
            for (int ntl = 0; ntl < 4; ++ntl) {
                int c = (4 * ni + ntl) * 8 + cbase;
                int off = il ? (((c >> 2) << 3) + (c & 3)) : c;
                float2 b2 = __ldg((const float2*)(bias + c));
                if (v0ok)
                    *(__half2*)(d0 + off) = __floats2half2_rn(acc[s * 4 + ntl][0] + b2.x,
                                                              acc[s * 4 + ntl][1] + b2.y);
                if (v1ok)
                    *(__half2*)(d1 + off) = __floats2half2_rn(acc[s * 4 + ntl][2] + b2.x,
                                                              acc[s * 4 + ntl][3] + b2.y);
            }
        }
        __syncthreads();   // all warps done with Bb before it gets overwritten
    }
}

// ---------------- K4: fused gather-attention + residual + LN (profiled) ------
__global__ void __launch_bounds__(256) k_attn(
    const float* __restrict__ x, const int* __restrict__ ntype,
    const float* __restrict__ rbias,
    const float* __restrict__ skip, const float* __restrict__ gamma,
    const float* __restrict__ beta, float* __restrict__ out, int N)
{
    __shared__ __align__(16) float s_rqk[3072];
    __shared__ __align__(16) float s_rvv[3072];
    __shared__ float s_rb[64];

    int tid = threadIdx.x;
    {
        const uint4* sq = (const uint4*)g_tqk;
        const uint4* sv = (const uint4*)g_tv;
        uint4* dq = (uint4*)s_rqk;
        uint4* dv = (uint4*)s_rvv;
        #pragma unroll 3
        for (int i = tid; i < 768; i += 256) { dq[i] = sq[i]; dv[i] = sv[i]; }
    }
    if (tid < 64) s_rb[tid] = rbias[tid];
    __syncthreads();

    int lane = tid & 31;
    int h = lane >> 2;

    for (;;) {
        int base = 0;
        if (lane == 0) base = atomicAdd(&g_wq, 4);
        base = __shfl_sync(0xffffffffu, base, 0);
        if (base >= N) break;
        int stop = base + 4; if (stop > N) stop = N;

        for (int n = base; n < stop; ++n) {
            float4 q4;
            {
                uint2 qr = *(const uint2*)(g_Qh + (size_t)n * 128 + lane * 4);
                __half2* qh = (__half2*)&qr;
                float2 q01 = __half22float2(qh[0]), q23 = __half22float2(qh[1]);
                q4 = make_float4(q01.x, q01.y, q23.x, q23.y);
            }
            int2 od = g_offdeg[n];
            int start = od.x;
            int deg = od.y;

            float4 oa = make_float4(0.f, 0.f, 0.f, 0.f);
            float z = 0.f;

            int j = 0;
            for (; j + 3 < deg; j += 4) {
                int2 p0 = g_epk[start + j + 0];
                int2 p1 = g_epk[start + j + 1];
                int2 p2 = g_epk[start + j + 2];
                int2 p3 = g_epk[start + j + 3];

                uint4 kv0 = *(const uint4*)(g_KVh + (size_t)(p0.x & 0x1FFFF) * 256 + lane * 8);
                uint4 kv1 = *(const uint4*)(g_KVh + (size_t)(p1.x & 0x1FFFF) * 256 + lane * 8);
                uint4 kv2 = *(const uint4*)(g_KVh + (size_t)(p2.x & 0x1FFFF) * 256 + lane * 8);
                uint4 kv3 = *(const uint4*)(g_KVh + (size_t)(p3.x & 0x1FFFF) * 256 + lane * 8);

                int cb0 = (((p0.x >> 17) & 31) << 7) + lane * 4;
                int cb1 = (((p1.x >> 17) & 31) << 7) + lane * 4;
                int cb2 = (((p2.x >> 17) & 31) << 7) + lane * 4;
                int cb3 = (((p3.x >> 17) & 31) << 7) + lane * 4;

                float4 rk0 = *(float4*)(s_rqk + cb0);
                float4 rk1 = *(float4*)(s_rqk + cb1);
                float4 rk2 = *(float4*)(s_rqk + cb2);
                float4 rk3 = *(float4*)(s_rqk + cb3);

                __half2* h0 = (__half2*)&kv0;
                __half2* h1 = (__half2*)&kv1;
                __half2* h2 = (__half2*)&kv2;
                __half2* h3 = (__half2*)&kv3;

                float2 k0a = __half22float2(h0[0]), k0b = __half22float2(h0[1]);
                float2 k1a = __half22float2(h1[0]), k1b = __half22float2(h1[1]);
                float2 k2a = __half22float2(h2[0]), k2b = __half22float2(h2[1]);
                float2 k3a = __half22float2(h3[0]), k3b = __half22float2(h3[1]);

                float s0 = q4.x * k0a.x * rk0.x + q4.y * k0a.y * rk0.y
                         + q4.z * k0b.x * rk0.z + q4.w * k0b.y * rk0.w;
                float s1 = q4.x * k1a.x * rk1.x + q4.y * k1a.y * rk1.y
                         + q4.z * k1b.x * rk1.z + q4.w * k1b.y * rk1.w;
                float s2 = q4.x * k2a.x * rk2.x + q4.y * k2a.y * rk2.y
                         + q4.z * k2b.x * rk2.z + q4.w * k2b.y * rk2.w;
                float s3 = q4.x * k3a.x * rk3.x + q4.y * k3a.y * rk3.y
                         + q4.z * k3b.x * rk3.z + q4.w * k3b.y * rk3.w;

                s0 += __shfl_xor_sync(0xffffffffu, s0, 1);
                s1 += __shfl_xor_sync(0xffffffffu, s1, 1);
                s2 += __shfl_xor_sync(0xffffffffu, s2, 1);
                s3 += __shfl_xor_sync(0xffffffffu, s3, 1);
                s0 += __shfl_xor_sync(0xffffffffu, s0, 2);
                s1 += __shfl_xor_sync(0xffffffffu, s1, 2);
                s2 += __shfl_xor_sync(0xffffffffu, s2, 2);
                s3 += __shfl_xor_sync(0xffffffffu, s3, 2);

                float e0 = __expf(s0 * 0.25f + s_rb[((p0.x >> 22) & 7) * 8 + h] + __int_as_float(p0.y));
                float e1 = __expf(s1 * 0.25f + s_rb[((p1.x >> 22) & 7) * 8 + h] + __int_as_float(p1.y));
                float e2 = __expf(s2 * 0.25f + s_rb[((p2.x >> 22) & 7) * 8 + h] + __int_as_float(p2.y));
                float e3 = __expf(s3 * 0.25f + s_rb[((p3.x >> 22) & 7) * 8 + h] + __int_as_float(p3.y));
                z += (e0 + e1) + (e2 + e3);

                float4 rv0 = *(float4*)(s_rvv + cb0);
                float4 rv1 = *(float4*)(s_rvv + cb1);
                float4 rv2 = *(float4*)(s_rvv + cb2);
                float4 rv3 = *(float4*)(s_rvv + cb3);

                float2 v0a = __half22float2(h0[2]), v0b = __half22float2(h0[3]);
                float2 v1a = __half22float2(h1[2]), v1b = __half22float2(h1[3]);
                float2 v2a = __half22float2(h2[2]), v2b = __half22float2(h2[3]);
                float2 v3a = __half22float2(h3[2]), v3b = __half22float2(h3[3]);

                oa.x += v0a.x * rv0.x * e0 + v1a.x * rv1.x * e1
                      + v2a.x * rv2.x * e2 + v3a.x * rv3.x * e3;
                oa.y += v0a.y * rv0.y * e0 + v1a.y * rv1.y * e1
                      + v2a.y * rv2.y * e2 + v3a.y * rv3.y * e3;
                oa.z += v0b.x * rv0.z * e0 + v1b.x * rv1.z * e1
                      + v2b.x * rv2.z * e2 + v3b.x * rv3.z * e3;
                oa.w += v0b.y * rv0.w * e0 + v1b.y * rv1.w * e1
                      + v2b.y * rv2.w * e2 + v3b.y * rv3.w * e3;
            }
            for (; j < deg; ++j) {
                int2 p = g_epk[start + j];
                uint4 kv = *(const uint4*)(g_KVh + (size_t)(p.x & 0x1FFFF) * 256 + lane * 8);
                int cb = (((p.x >> 17) & 31) << 7) + lane * 4;
                float4 rk4 = *(float4*)(s_rqk + cb);
                float4 rv4 = *(float4*)(s_rvv + cb);

                __half2* hh = (__half2*)&kv;
                float2 k01 = __half22float2(hh[0]), k23 = __half22float2(hh[1]);
                float2 v01 = __half22float2(hh[2]), v23 = __half22float2(hh[3]);

                float sc = q4.x * k01.x * rk4.x + q4.y * k01.y * rk4.y
                         + q4.z * k23.x * rk4.z + q4.w * k23.y * rk4.w;
                sc += __shfl_xor_sync(0xffffffffu, sc, 1);
                sc += __shfl_xor_sync(0xffffffffu, sc, 2);

                float es = __expf(sc * 0.25f + s_rb[((p.x >> 22) & 7) * 8 + h] + __int_as_float(p.y));
                z += es;
                oa.x += v01.x * rv4.x * es;
                oa.y += v01.y * rv4.y * es;
                oa.z += v23.x * rv4.z * es;
                oa.w += v23.y * rv4.w * es;
            }

            int t = ntype[n];
            float a = 1.f / (1.f + __expf(-__ldg(skip + t)));
            float b = 1.f - a;
            float r = a / (z + 1e-9f);

            float4 xi = *(const float4*)(x + (size_t)n * 128 + lane * 4);
            float4 xv;
            xv.x = oa.x * r + b * xi.x;
            xv.y = oa.y * r + b * xi.y;
            xv.z = oa.z * r + b * xi.z;
            xv.w = oa.w * r + b * xi.w;

            float s = xv.x + xv.y + xv.z + xv.w;
            #pragma unroll
            for (int o = 16; o; o >>= 1) s += __shfl_xor_sync(0xffffffffu, s, o);
            float mu = s * (1.f / 128.f);

            float dx0 = xv.x - mu, dx1 = xv.y - mu, dx2 = xv.z - mu, dx3 = xv.w - mu;
            float vs = dx0 * dx0 + dx1 * dx1 + dx2 * dx2 + dx3 * dx3;
            #pragma unroll
            for (int o = 16; o; o >>= 1) vs += __shfl_xor_sync(0xffffffffu, vs, o);
            float rs = rsqrtf(vs * (1.f / 128.f) + 1e-5f);

            float4 g4 = *(const float4*)(gamma + t * 128 + lane * 4);
            float4 be4 = *(const float4*)(beta + t * 128 + lane * 4);

            float4 y;
            y.x = dx0 * rs * g4.x + be4.x;
            y.y = dx1 * rs * g4.y + be4.y;
            y.z = dx2 * rs * g4.z + be4.z;
            y.w = dx3 * rs * g4.w + be4.w;

            *(float4*)(out + (size_t)n * 128 + lane * 4) = y;
        }
    }

    // tail: re-zero build state for the next graph replay (no reader races:
    // attn reads g_offdeg, never g_deg / g_cnt)
    int gi = blockIdx.x * blockDim.x + tid;
    if (gi < N) g_deg[gi] = 0;
    if (gi < 3) g_cnt[gi] = 0;
}

// ---------------- launch ----------------
extern "C" void kernel_launch(void* const* d_in, const int* in_sizes, int n_in,
                              void* d_out, int out_size)
{
    const float* node_inp   = (const float*)d_in[0];
    const int*   node_type  = (const int*)d_in[1];
    const int*   edge_index = (const int*)d_in[2];
    const int*   edge_type  = (const int*)d_in[3];
    const int*   edge_sign  = (const int*)d_in[4];
    const float* edge_dist  = (const float*)d_in[5];
    const float* Wq = (const float*)d_in[6];
    const float* bq = (const float*)d_in[7];
    const float* Wk = (const float*)d_in[8];
    const float* bk = (const float*)d_in[9];
    const float* Wv = (const float*)d_in[10];
    const float* bv = (const float*)d_in[11];
    const float* rel_q   = (const float*)d_in[12];
    const float* rel_k   = (const float*)d_in[13];
    const float* rel_v   = (const float*)d_in[14];
    const float* rel_b   = (const float*)d_in[15];
    const float* skf     = (const float*)d_in[16];
    const float* svf     = (const float*)d_in[17];
    const float* skn     = (const float*)d_in[18];
    const float* svn     = (const float*)d_in[19];
    const float* d_alpha = (const float*)d_in[20];
    const float* d_tau   = (const float*)d_in[21];
    const float* skip    = (const float*)d_in[22];
    const float* ln_g    = (const float*)d_in[23];
    const float* ln_b    = (const float*)d_in[24];

    int N = in_sizes[1];
    int E = in_sizes[3];

    float* out = (float*)d_out;

    cudaFuncSetAttribute(k_qkv_es, cudaFuncAttributeMaxDynamicSharedMemorySize, SM_TOTAL);

    int nb = (N + 255) / 256;
    int eb = (E + 255) / 256;
    int eb512 = (E + 511) / 512;
    int qb = (N + 127) / 128;

    k_histpack<<<eb + 72, 256>>>(node_type, edge_index, Wq, Wk, Wv,
                                 rel_q, rel_k, rel_v, skf, svf, skn, svn, N, E, eb);
    k_off<<<nb, 256>>>(node_type, N);
    k_qkv_es<<<eb512 + qb, 512, SM_TOTAL>>>(node_inp, node_type, bq, bk, bv,
                                            edge_index, edge_type, edge_sign, edge_dist,
                                            d_alpha, d_tau, N, E, eb512);
    k_attn<<<444, 256>>>(node_inp, node_type, rel_b, skip, ln_g, ln_b, out, N);
}

// round 14
// speedup vs baseline: 1.1194x; 1.1194x over previous
#include <cuda_runtime.h>
#include <cuda_fp16.h>
#include <cstdint>

#define NMAX 100000
#define EMAX 800000

// -------- scratch (static __device__, no allocation) --------
__device__ __half g_Qh[NMAX * 128];
__device__ __half g_KVh[NMAX * 256];   // interleaved: [k0..3 v0..3 k4..7 v4..7 ...]
__device__ int   g_perm[NMAX];
__device__ int   g_cnt[3];
__device__ int   g_cnt2[3];
__device__ int   g_total;
__device__ int   g_wq;                 // dynamic work cursor for attn
// CSR by destination
__device__ int   g_deg[NMAX];
__device__ __align__(8) int2 g_offdeg[NMAX];  // {offset, degree} for attn
__device__ int   g_cur2[NMAX];
__device__ __align__(8) int2 g_epk[EMAX];   // {src|comb<<17|et<<22, phi_bits}
// pre-packed fp16 weights in mma.sync B-fragment order
__device__ __align__(16) uint4 g_Bpk[3][3][2048];
// precomputed rel/sign tables: [et*3+sidx][128]
__device__ __align__(16) float g_tqk[3072];
__device__ __align__(16) float g_tv[3072];

// ---------------- helpers ----------------
__device__ __forceinline__ uint32_t pack_half(float a, float b) {
    __half2 t = __floats2half2_rn(a, b);
    return *(uint32_t*)&t;
}

__device__ __forceinline__ void mma16816h(float* c,
    uint32_t a0, uint32_t a1, uint32_t a2, uint32_t a3,
    uint32_t b0, uint32_t b1)
{
    asm volatile(
        "mma.sync.aligned.m16n8k16.row.col.f32.f16.f16.f32 "
        "{%0,%1,%2,%3}, {%4,%5,%6,%7}, {%8,%9}, {%0,%1,%2,%3};"
        : "+f"(c[0]), "+f"(c[1]), "+f"(c[2]), "+f"(c[3])
        : "r"(a0), "r"(a1), "r"(a2), "r"(a3), "r"(b0), "r"(b1));
}

__device__ __forceinline__ uint32_t s2u(const void* p) {
    uint32_t a;
    asm("{ .reg .u64 t; cvta.to.shared.u64 t, %1; cvt.u32.u64 %0, t; }" : "=r"(a) : "l"(p));
    return a;
}

__device__ __forceinline__ void cp16(uint32_t s, const void* g) {
    asm volatile("cp.async.cg.shared.global [%0], [%1], 16;" :: "r"(s), "l"(g));
}

// ---------------- K1: fused histograms + weight pack + tables ----------------
__global__ void k_histpack(const int* __restrict__ ntype, const int* __restrict__ ei,
                           const float* __restrict__ Wq, const float* __restrict__ Wk,
                           const float* __restrict__ Wv,
                           const float* __restrict__ rq, const float* __restrict__ rk,
                           const float* __restrict__ rv,
                           const float* __restrict__ skf, const float* __restrict__ svf,
                           const float* __restrict__ skn, const float* __restrict__ svn,
                           int N, int E, int EB)
{
    int tid = threadIdx.x;
    if ((int)blockIdx.x < EB) {
        __shared__ int h[3];
        if (tid < 3) h[tid] = 0;
        __syncthreads();
        int i = blockIdx.x * blockDim.x + tid;
        if (i < N) atomicAdd(&h[ntype[i]], 1);
        if (i < E) atomicAdd(&g_deg[ei[E + i]], 1);
        __syncthreads();
        if (tid < 3 && h[tid]) atomicAdd(&g_cnt[tid], h[tid]);
        return;
    }

    if ((int)blockIdx.x == EB) {
        if (tid == 0) g_total = 0;
        if (tid < 3) g_cnt2[tid] = 0;
    }

    int gid = (blockIdx.x - EB) * blockDim.x + tid;
    if (gid < 3072) {
        int c = gid >> 7, d = gid & 127;
        int et = c / 3, s = c - et * 3;
        float sk = (s < 2) ? skf[s * 128 + d] : skn[d];
        float sv = (s < 2) ? svf[s * 128 + d] : svn[d];
        g_tqk[gid] = rq[et * 128 + d] * rk[et * 128 + d] * sk;
        g_tv[gid]  = rv[et * 128 + d] * sv;
    }
    if (gid >= 3 * 3 * 2048) return;
    int t = gid / 6144;
    int m = (gid % 6144) / 2048;
    int w = gid % 2048;
    int kt = w >> 8;
    int np = (w >> 5) & 7;
    int lane = w & 31;

    const float* W = (m == 0 ? Wq : (m == 1 ? Wk : Wv)) + (size_t)t * 16384;
    int k0 = kt * 16 + (lane & 3) * 2;
    int n0 = (2 * np) * 8 + (lane >> 2);

    uint4 hi;
    uint32_t* hp = (uint32_t*)&hi;
    #pragma unroll
    for (int j = 0; j < 2; ++j) {
        int n = n0 + j * 8;
        #pragma unroll
        for (int g = 0; g < 2; ++g) {
            float v0 = W[(k0 + g * 8) * 128 + n];
            float v1 = W[(k0 + g * 8 + 1) * 128 + n];
            hp[j * 2 + g] = pack_half(v0, v1);
        }
    }
    g_Bpk[t][m][w] = hi;
}

// ---------------- K2: CSR offsets + type-scatter ----------------
__global__ void __launch_bounds__(256) k_off(const int* __restrict__ ntype, int N) {
    __shared__ int sws[8];
    __shared__ int sbase;
    __shared__ int h[3], tb[3];

    int tid = threadIdx.x;
    int lane = tid & 31, w = tid >> 5;
    int i = blockIdx.x * 256 + tid;
    int d = (i < N) ? g_deg[i] : 0;

    if (blockIdx.x == 0 && tid == 0) g_wq = 0;   // for k_attn (launch-ordered)

    int inc = d;
    #pragma unroll
    for (int o = 1; o < 32; o <<= 1) {
        int t = __shfl_up_sync(0xffffffffu, inc, o);
        if (lane >= o) inc += t;
    }
    if (lane == 31) sws[w] = inc;
    if (tid < 3) h[tid] = 0;
    __syncthreads();
    if (tid == 0) {
        int run = 0;
        #pragma unroll
        for (int k = 0; k < 8; ++k) { int t = sws[k]; sws[k] = run; run += t; }
        sbase = atomicAdd(&g_total, run);
    }
    __syncthreads();
    int ex = sbase + sws[w] + inc - d;
    if (i < N) {
        g_offdeg[i] = make_int2(ex, d);
        g_cur2[i] = ex;
    }

    int t = 0, r = 0;
    if (i < N) { t = ntype[i]; r = atomicAdd(&h[t], 1); }
    __syncthreads();
    if (tid < 3 && h[tid]) tb[tid] = atomicAdd(&g_cnt2[tid], h[tid]);
    __syncthreads();
    if (i < N) {
        int base = (t == 0) ? 0 : ((t == 1) ? g_cnt[0] : (g_cnt[0] + g_cnt[1]));
        g_perm[base + tb[t] + r] = i;
    }
}

// ---------------- K3: edge payload scatter (lightweight, no smem) ------------
__global__ void k_escatter(const int* __restrict__ ei, const int* __restrict__ etype,
                           const int* __restrict__ esign, const float* __restrict__ edist,
                           const float* __restrict__ alphap, const float* __restrict__ taup,
                           int E)
{
    int e = blockIdx.x * blockDim.x + threadIdx.x;
    if (e >= E) return;
    int dst = ei[E + e];
    int src = ei[e];
    int et = etype[e];
    int sg = esign[e];
    int sidx = (sg == -1) ? 0 : ((sg == 1) ? 1 : 2);
    float alpha = __ldg(alphap);
    float itau = 1.f / (__ldg(taup) + 1e-9f);
    float phi = alpha * __expf(-edist[e] * itau);
    int pos = atomicAdd(&g_cur2[dst], 1);
    int w = src | ((et * 3 + sidx) << 17) | (et << 22);
    g_epk[pos] = make_int2(w, __float_as_int(phi));
}

// ---------------- K4: tensor-core QKV (profiled), 32x32 warp tiles ------------
#define SM_B0 0
#define SM_B1 32768
#define SM_STAGE 65536
#define SM_META (65536 + 33792)
#define SM_TOTAL (SM_META + 1024)

__device__ __forceinline__ void copyB(uint32_t dst, const uint4* src, int tid) {
    #pragma unroll
    for (int i = tid; i < 2048; i += 512) cp16(dst + i * 16, src + i);
    asm volatile("cp.async.commit_group;");
}

__global__ void __launch_bounds__(512) k_qkv_mma(
    const float* __restrict__ x, const int* __restrict__ ntype,
    const float* __restrict__ bq, const float* __restrict__ bk,
    const float* __restrict__ bv, int N)
{
    extern __shared__ __align__(16) unsigned char sm[];
    uint32_t smb = s2u(sm);
    float* raw = (float*)(sm + SM_STAGE);     // 64 rows x 132 floats
    int* sp = (int*)(sm + SM_META);
    int* st = sp + 128;

    int tid = threadIdx.x;
    int wid = tid >> 5;
    int lane = tid & 31;
    int mi = wid & 3;
    int ni = wid >> 2;

    int start = blockIdx.x * 128;
    int count = N - start; if (count > 128) count = 128;

    if (tid < count) {
        int pn = g_perm[start + tid];
        sp[tid] = pn;
        st[tid] = ntype[pn];
    }
    __syncthreads();

    int tmin = st[0], tmax = st[count - 1];
    int niter = 3 * (tmax - tmin + 1);

    copyB(smb + SM_B0, g_Bpk[tmin][0], tid);

    // A fragments -> registers: warp covers rows mi*32..+32 (2 m-subtiles)
    uint4 a2[8][2];
    #pragma unroll
    for (int chunk = 0; chunk < 2; ++chunk) {
        for (int i = tid; i < 2048; i += 512) {
            int row = i >> 5, col = i & 31;
            int gr = chunk * 64 + row;
            float4 v = make_float4(0.f, 0.f, 0.f, 0.f);
            if (gr < count) v = *(const float4*)(x + (size_t)sp[gr] * 128 + col * 4);
            *(float4*)(raw + row * 132 + col * 4) = v;
        }
        __syncthreads();
        if ((mi >> 1) == chunk) {
            int q2 = (lane & 3) * 2;
            #pragma unroll
            for (int s = 0; s < 2; ++s) {
                int lr = (mi & 1) * 32 + s * 16 + (lane >> 2);
                #pragma unroll
                for (int kt = 0; kt < 8; ++kt) {
                    const float* b0 = raw + lr * 132 + kt * 16 + q2;
                    float2 f00 = *(const float2*)(b0);
                    float2 f10 = *(const float2*)(b0 + 8 * 132);
                    float2 f01 = *(const float2*)(b0 + 8);
                    float2 f11 = *(const float2*)(b0 + 8 * 132 + 8);
                    a2[kt][s].x = pack_half(f00.x, f00.y);
                    a2[kt][s].y = pack_half(f10.x, f10.y);
                    a2[kt][s].z = pack_half(f01.x, f01.y);
                    a2[kt][s].w = pack_half(f11.x, f11.y);
                }
            }
        }
        __syncthreads();
    }

    for (int it = 0; it < niter; ++it) {
        int t = tmin + it / 3;
        int m = it % 3;
        uint4* Bb = (uint4*)(sm + ((it & 1) ? SM_B1 : SM_B0));

        if (it + 1 < niter) {
            int t2 = tmin + (it + 1) / 3;
            int m2 = (it + 1) % 3;
            copyB(smb + ((it & 1) ? SM_B0 : SM_B1), g_Bpk[t2][m2], tid);
            asm volatile("cp.async.wait_group 1;" ::: "memory");
        } else {
            asm volatile("cp.async.wait_group 0;" ::: "memory");
        }
        __syncthreads();

        float acc[8][4];
        #pragma unroll
        for (int i = 0; i < 8; ++i)
            #pragma unroll
            for (int j = 0; j < 4; ++j) acc[i][j] = 0.f;

        #pragma unroll
        for (int kt = 0; kt < 8; ++kt) {
            uint4 b0 = Bb[(kt * 8 + 2 * ni) * 32 + lane];
            uint4 b1 = Bb[(kt * 8 + 2 * ni + 1) * 32 + lane];
            #pragma unroll
            for (int s = 0; s < 2; ++s) {
                uint4 ah = a2[kt][s];
                mma16816h(acc[s * 4 + 0], ah.x, ah.y, ah.z, ah.w, b0.x, b0.y);
                mma16816h(acc[s * 4 + 1], ah.x, ah.y, ah.z, ah.w, b0.z, b0.w);
                mma16816h(acc[s * 4 + 2], ah.x, ah.y, ah.z, ah.w, b1.x, b1.y);
                mma16816h(acc[s * 4 + 3], ah.x, ah.y, ah.z, ah.w, b1.z, b1.w);
            }
        }

        // ---- epilogue (fp16 outputs) ----
        const float* bias = (m == 0 ? bq : (m == 1 ? bk : bv)) + t * 128;
        int cbase = (lane & 3) * 2;
        int moff = (m == 2) ? 4 : 0;
        bool il = (m != 0);

        #pragma unroll
        for (int s = 0; s < 2; ++s) {
            int row0 = mi * 32 + s * 16 + (lane >> 2);
            int row1 = row0 + 8;
            bool v0ok = (row0 < count) && (st[row0] == t);
            bool v1ok = (row1 < count) && (st[row1] == t);
            __half* d0 = nullptr;
            __half* d1 = nullptr;
            if (il) {
                if (v0ok) d0 = g_KVh + (size_t)sp[row0] * 256 + moff;
                if (v1ok) d1 = g_KVh + (size_t)sp[row1] * 256 + moff;
            } else {
                if (v0ok) d0 = g_Qh + (size_t)sp[row0] * 128;
                if (v1ok) d1 = g_Qh + (size_t)sp[row1] * 128;
            }
            #pragma unroll
            for (int ntl = 0; ntl < 4; ++ntl) {
                int c = (4 * ni + ntl) * 8 + cbase;
                int off = il ? (((c >> 2) << 3) + (c & 3)) : c;
                float2 b2 = __ldg((const float2*)(bias + c));
                if (v0ok)
                    *(__half2*)(d0 + off) = __floats2half2_rn(acc[s * 4 + ntl][0] + b2.x,
                                                              acc[s * 4 + ntl][1] + b2.y);
                if (v1ok)
                    *(__half2*)(d1 + off) = __floats2half2_rn(acc[s * 4 + ntl][2] + b2.x,
                                                              acc[s * 4 + ntl][3] + b2.y);
            }
        }
        __syncthreads();
    }
}

// ---------------- K5: fused gather-attention + residual + LN ------------------
__global__ void __launch_bounds__(256) k_attn(
    const float* __restrict__ x, const int* __restrict__ ntype,
    const float* __restrict__ rbias,
    const float* __restrict__ skip, const float* __restrict__ gamma,
    const float* __restrict__ beta, float* __restrict__ out, int N)
{
    __shared__ __align__(16) float s_rqk[3072];
    __shared__ __align__(16) float s_rvv[3072];
    __shared__ float s_rb[64];

    int tid = threadIdx.x;
    {
        const uint4* sq = (const uint4*)g_tqk;
        const uint4* sv = (const uint4*)g_tv;
        uint4* dq = (uint4*)s_rqk;
        uint4* dv = (uint4*)s_rvv;
        #pragma unroll 3
        for (int i = tid; i < 768; i += 256) { dq[i] = sq[i]; dv[i] = sv[i]; }
    }
    if (tid < 64) s_rb[tid] = rbias[tid];
    __syncthreads();

    int lane = tid & 31;
    int h = lane >> 2;

    for (;;) {
        int base = 0;
        if (lane == 0) base = atomicAdd(&g_wq, 4);
        base = __shfl_sync(0xffffffffu, base, 0);
        if (base >= N) break;
        int stop = base + 4; if (stop > N) stop = N;

        for (int n = base; n < stop; ++n) {
            float4 q4;
            {
                uint2 qr = *(const uint2*)(g_Qh + (size_t)n * 128 + lane * 4);
                __half2* qh = (__half2*)&qr;
                float2 q01 = __half22float2(qh[0]), q23 = __half22float2(qh[1]);
                q4 = make_float4(q01.x, q01.y, q23.x, q23.y);
            }
            int2 od = g_offdeg[n];
            int start = od.x;
            int deg = od.y;

            float4 oa = make_float4(0.f, 0.f, 0.f, 0.f);
            float z = 0.f;

            int j = 0;
            for (; j + 3 < deg; j += 4) {
                int2 p0 = g_epk[start + j + 0];
                int2 p1 = g_epk[start + j + 1];
                int2 p2 = g_epk[start + j + 2];
                int2 p3 = g_epk[start + j + 3];

                uint4 kv0 = *(const uint4*)(g_KVh + (size_t)(p0.x & 0x1FFFF) * 256 + lane * 8);
                uint4 kv1 = *(const uint4*)(g_KVh + (size_t)(p1.x & 0x1FFFF) * 256 + lane * 8);
                uint4 kv2 = *(const uint4*)(g_KVh + (size_t)(p2.x & 0x1FFFF) * 256 + lane * 8);
                uint4 kv3 = *(const uint4*)(g_KVh + (size_t)(p3.x & 0x1FFFF) * 256 + lane * 8);

                int cb0 = (((p0.x >> 17) & 31) << 7) + lane * 4;
                int cb1 = (((p1.x >> 17) & 31) << 7) + lane * 4;
                int cb2 = (((p2.x >> 17) & 31) << 7) + lane * 4;
                int cb3 = (((p3.x >> 17) & 31) << 7) + lane * 4;

                float4 rk0 = *(float4*)(s_rqk + cb0);
                float4 rk1 = *(float4*)(s_rqk + cb1);
                float4 rk2 = *(float4*)(s_rqk + cb2);
                float4 rk3 = *(float4*)(s_rqk + cb3);

                __half2* h0 = (__half2*)&kv0;
                __half2* h1 = (__half2*)&kv1;
                __half2* h2 = (__half2*)&kv2;
                __half2* h3 = (__half2*)&kv3;

                float2 k0a = __half22float2(h0[0]), k0b = __half22float2(h0[1]);
                float2 k1a = __half22float2(h1[0]), k1b = __half22float2(h1[1]);
                float2 k2a = __half22float2(h2[0]), k2b = __half22float2(h2[1]);
                float2 k3a = __half22float2(h3[0]), k3b = __half22float2(h3[1]);

                float s0 = q4.x * k0a.x * rk0.x + q4.y * k0a.y * rk0.y
                         + q4.z * k0b.x * rk0.z + q4.w * k0b.y * rk0.w;
                float s1 = q4.x * k1a.x * rk1.x + q4.y * k1a.y * rk1.y
                         + q4.z * k1b.x * rk1.z + q4.w * k1b.y * rk1.w;
                float s2 = q4.x * k2a.x * rk2.x + q4.y * k2a.y * rk2.y
                         + q4.z * k2b.x * rk2.z + q4.w * k2b.y * rk2.w;
                float s3 = q4.x * k3a.x * rk3.x + q4.y * k3a.y * rk3.y
                         + q4.z * k3b.x * rk3.z + q4.w * k3b.y * rk3.w;

                s0 += __shfl_xor_sync(0xffffffffu, s0, 1);
                s1 += __shfl_xor_sync(0xffffffffu, s1, 1);
                s2 += __shfl_xor_sync(0xffffffffu, s2, 1);
                s3 += __shfl_xor_sync(0xffffffffu, s3, 1);
                s0 += __shfl_xor_sync(0xffffffffu, s0, 2);
                s1 += __shfl_xor_sync(0xffffffffu, s1, 2);
                s2 += __shfl_xor_sync(0xffffffffu, s2, 2);
                s3 += __shfl_xor_sync(0xffffffffu, s3, 2);

                float e0 = __expf(s0 * 0.25f + s_rb[((p0.x >> 22) & 7) * 8 + h] + __int_as_float(p0.y));
                float e1 = __expf(s1 * 0.25f + s_rb[((p1.x >> 22) & 7) * 8 + h] + __int_as_float(p1.y));
                float e2 = __expf(s2 * 0.25f + s_rb[((p2.x >> 22) & 7) * 8 + h] + __int_as_float(p2.y));
                float e3 = __expf(s3 * 0.25f + s_rb[((p3.x >> 22) & 7) * 8 + h] + __int_as_float(p3.y));
                z += (e0 + e1) + (e2 + e3);

                float4 rv0 = *(float4*)(s_rvv + cb0);
                float4 rv1 = *(float4*)(s_rvv + cb1);
                float4 rv2 = *(float4*)(s_rvv + cb2);
                float4 rv3 = *(float4*)(s_rvv + cb3);

                float2 v0a = __half22float2(h0[2]), v0b = __half22float2(h0[3]);
                float2 v1a = __half22float2(h1[2]), v1b = __half22float2(h1[3]);
                float2 v2a = __half22float2(h2[2]), v2b = __half22float2(h2[3]);
                float2 v3a = __half22float2(h3[2]), v3b = __half22float2(h3[3]);

                oa.x += v0a.x * rv0.x * e0 + v1a.x * rv1.x * e1
                      + v2a.x * rv2.x * e2 + v3a.x * rv3.x * e3;
                oa.y += v0a.y * rv0.y * e0 + v1a.y * rv1.y * e1
                      + v2a.y * rv2.y * e2 + v3a.y * rv3.y * e3;
                oa.z += v0b.x * rv0.z * e0 + v1b.x * rv1.z * e1
                      + v2b.x * rv2.z * e2 + v3b.x * rv3.z * e3;
                oa.w += v0b.y * rv0.w * e0 + v1b.y * rv1.w * e1
                      + v2b.y * rv2.w * e2 + v3b.y * rv3.w * e3;
            }
            for (; j < deg; ++j) {
                int2 p = g_epk[start + j];
                uint4 kv = *(const uint4*)(g_KVh + (size_t)(p.x & 0x1FFFF) * 256 + lane * 8);
                int cb = (((p.x >> 17) & 31) << 7) + lane * 4;
                float4 rk4 = *(float4*)(s_rqk + cb);
                float4 rv4 = *(float4*)(s_rvv + cb);

                __half2* hh = (__half2*)&kv;
                float2 k01 = __half22float2(hh[0]), k23 = __half22float2(hh[1]);
                float2 v01 = __half22float2(hh[2]), v23 = __half22float2(hh[3]);

                float sc = q4.x * k01.x * rk4.x + q4.y * k01.y * rk4.y
                         + q4.z * k23.x * rk4.z + q4.w * k23.y * rk4.w;
                sc += __shfl_xor_sync(0xffffffffu, sc, 1);
                sc += __shfl_xor_sync(0xffffffffu, sc, 2);

                float es = __expf(sc * 0.25f + s_rb[((p.x >> 22) & 7) * 8 + h] + __int_as_float(p.y));
                z += es;
                oa.x += v01.x * rv4.x * es;
                oa.y += v01.y * rv4.y * es;
                oa.z += v23.x * rv4.z * es;
                oa.w += v23.y * rv4.w * es;
            }

            int t = ntype[n];
            float a = 1.f / (1.f + __expf(-__ldg(skip + t)));
            float b = 1.f - a;
            float r = a / (z + 1e-9f);

            float4 xi = *(const float4*)(x + (size_t)n * 128 + lane * 4);
            float4 xv;
            xv.x = oa.x * r + b * xi.x;
            xv.y = oa.y * r + b * xi.y;
            xv.z = oa.z * r + b * xi.z;
            xv.w = oa.w * r + b * xi.w;

            float s = xv.x + xv.y + xv.z + xv.w;
            #pragma unroll
            for (int o = 16; o; o >>= 1) s += __shfl_xor_sync(0xffffffffu, s, o);
            float mu = s * (1.f / 128.f);

            float dx0 = xv.x - mu, dx1 = xv.y - mu, dx2 = xv.z - mu, dx3 = xv.w - mu;
            float vs = dx0 * dx0 + dx1 * dx1 + dx2 * dx2 + dx3 * dx3;
            #pragma unroll
            for (int o = 16; o; o >>= 1) vs += __shfl_xor_sync(0xffffffffu, vs, o);
            float rs = rsqrtf(vs * (1.f / 128.f) + 1e-5f);

            float4 g4 = *(const float4*)(gamma + t * 128 + lane * 4);
            float4 be4 = *(const float4*)(beta + t * 128 + lane * 4);

            float4 y;
            y.x = dx0 * rs * g4.x + be4.x;
            y.y = dx1 * rs * g4.y + be4.y;
            y.z = dx2 * rs * g4.z + be4.z;
            y.w = dx3 * rs * g4.w + be4.w;

            *(float4*)(out + (size_t)n * 128 + lane * 4) = y;
        }
    }

    // tail: re-zero build state for the next graph replay
    int gi = blockIdx.x * blockDim.x + tid;
    if (gi < N) g_deg[gi] = 0;
    if (gi < 3) g_cnt[gi] = 0;
}

// ---------------- launch ----------------
extern "C" void kernel_launch(void* const* d_in, const int* in_sizes, int n_in,
                              void* d_out, int out_size)
{
    const float* node_inp   = (const float*)d_in[0];
    const int*   node_type  = (const int*)d_in[1];
    const int*   edge_index = (const int*)d_in[2];
    const int*   edge_type  = (const int*)d_in[3];
    const int*   edge_sign  = (const int*)d_in[4];
    const float* edge_dist  = (const float*)d_in[5];
    const float* Wq = (const float*)d_in[6];
    const float* bq = (const float*)d_in[7];
    const float* Wk = (const float*)d_in[8];
    const float* bk = (const float*)d_in[9];
    const float* Wv = (const float*)d_in[10];
    const float* bv = (const float*)d_in[11];
    const float* rel_q   = (const float*)d_in[12];
    const float* rel_k   = (const float*)d_in[13];
    const float* rel_v   = (const float*)d_in[14];
    const float* rel_b   = (const float*)d_in[15];
    const float* skf     = (const float*)d_in[16];
    const float* svf     = (const float*)d_in[17];
    const float* skn     = (const float*)d_in[18];
    const float* svn     = (const float*)d_in[19];
    const float* d_alpha = (const float*)d_in[20];
    const float* d_tau   = (const float*)d_in[21];
    const float* skip    = (const float*)d_in[22];
    const float* ln_g    = (const float*)d_in[23];
    const float* ln_b    = (const float*)d_in[24];

    int N = in_sizes[1];
    int E = in_sizes[3];

    float* out = (float*)d_out;

    cudaFuncSetAttribute(k_qkv_mma, cudaFuncAttributeMaxDynamicSharedMemorySize, SM_TOTAL);

    int nb = (N + 255) / 256;
    int eb = (E + 255) / 256;
    int qb = (N + 127) / 128;

    k_histpack<<<eb + 72, 256>>>(node_type, edge_index, Wq, Wk, Wv,
                                 rel_q, rel_k, rel_v, skf, svf, skn, svn, N, E, eb);
    k_off<<<nb, 256>>>(node_type, N);
    k_escatter<<<eb, 256>>>(edge_index, edge_type, edge_sign, edge_dist,
                            d_alpha, d_tau, E);
    k_qkv_mma<<<qb, 512, SM_TOTAL>>>(node_inp, node_type, bq, bk, bv, N);
    k_attn<<<740, 256>>>(node_inp, node_type, rel_b, skip, ln_g, ln_b, out, N);
}

// round 15
// speedup vs baseline: 1.1982x; 1.0704x over previous
#include <cuda_runtime.h>
#include <cuda_fp16.h>
#include <cstdint>

#define NMAX 100000
#define EMAX 800000

// -------- scratch (static __device__, no allocation) --------
__device__ __half g_Qh[NMAX * 128];
__device__ __half g_KVh[NMAX * 256];   // interleaved: [k0..3 v0..3 k4..7 v4..7 ...]
__device__ int   g_perm[NMAX];
__device__ int   g_cnt[3];
__device__ int   g_cnt2[3];
__device__ int   g_total;
__device__ int   g_wq;                 // dynamic work cursor for attn
// CSR by destination
__device__ int   g_deg[NMAX];
__device__ __align__(8) int2 g_offdeg[NMAX];  // {offset, degree} for attn
__device__ int   g_cur2[NMAX];
__device__ __align__(8) int2 g_epk[EMAX];   // {src|comb<<17|et<<22, phi_bits}
// pre-packed fp16 weights in mma.sync B-fragment order
__device__ __align__(16) uint4 g_Bpk[3][3][2048];
// precomputed rel/sign tables: [et*3+sidx][128]
__device__ __align__(16) float g_tqk[3072];
__device__ __align__(16) float g_tv[3072];

// ---------------- helpers ----------------
__device__ __forceinline__ uint32_t pack_half(float a, float b) {
    __half2 t = __floats2half2_rn(a, b);
    return *(uint32_t*)&t;
}

__device__ __forceinline__ void mma16816h(float* c,
    uint32_t a0, uint32_t a1, uint32_t a2, uint32_t a3,
    uint32_t b0, uint32_t b1)
{
    asm volatile(
        "mma.sync.aligned.m16n8k16.row.col.f32.f16.f16.f32 "
        "{%0,%1,%2,%3}, {%4,%5,%6,%7}, {%8,%9}, {%0,%1,%2,%3};"
        : "+f"(c[0]), "+f"(c[1]), "+f"(c[2]), "+f"(c[3])
        : "r"(a0), "r"(a1), "r"(a2), "r"(a3), "r"(b0), "r"(b1));
}

__device__ __forceinline__ uint32_t s2u(const void* p) {
    uint32_t a;
    asm("{ .reg .u64 t; cvta.to.shared.u64 t, %1; cvt.u32.u64 %0, t; }" : "=r"(a) : "l"(p));
    return a;
}

__device__ __forceinline__ void cp16(uint32_t s, const void* g) {
    asm volatile("cp.async.cg.shared.global [%0], [%1], 16;" :: "r"(s), "l"(g));
}

// ---------------- K1: fused histograms + weight pack + tables ----------------
__global__ void k_histpack(const int* __restrict__ ntype, const int* __restrict__ ei,
                           const float* __restrict__ Wq, const float* __restrict__ Wk,
                           const float* __restrict__ Wv,
                           const float* __restrict__ rq, const float* __restrict__ rk,
                           const float* __restrict__ rv,
                           const float* __restrict__ skf, const float* __restrict__ svf,
                           const float* __restrict__ skn, const float* __restrict__ svn,
                           int N, int E, int EB)
{
    int tid = threadIdx.x;
    if ((int)blockIdx.x < EB) {
        __shared__ int h[3];
        if (tid < 3) h[tid] = 0;
        __syncthreads();
        int i = blockIdx.x * blockDim.x + tid;
        if (i < N) atomicAdd(&h[ntype[i]], 1);
        if (i < E) atomicAdd(&g_deg[ei[E + i]], 1);
        __syncthreads();
        if (tid < 3 && h[tid]) atomicAdd(&g_cnt[tid], h[tid]);
        return;
    }

    if ((int)blockIdx.x == EB) {
        if (tid == 0) g_total = 0;
        if (tid < 3) g_cnt2[tid] = 0;
    }

    int gid = (blockIdx.x - EB) * blockDim.x + tid;
    if (gid < 3072) {
        int c = gid >> 7, d = gid & 127;
        int et = c / 3, s = c - et * 3;
        float sk = (s < 2) ? skf[s * 128 + d] : skn[d];
        float sv = (s < 2) ? svf[s * 128 + d] : svn[d];
        g_tqk[gid] = rq[et * 128 + d] * rk[et * 128 + d] * sk;
        g_tv[gid]  = rv[et * 128 + d] * sv;
    }
    if (gid >= 3 * 3 * 2048) return;
    int t = gid / 6144;
    int m = (gid % 6144) / 2048;
    int w = gid % 2048;
    int kt = w >> 8;
    int np = (w >> 5) & 7;
    int lane = w & 31;

    const float* W = (m == 0 ? Wq : (m == 1 ? Wk : Wv)) + (size_t)t * 16384;
    int k0 = kt * 16 + (lane & 3) * 2;
    int n0 = (2 * np) * 8 + (lane >> 2);

    uint4 hi;
    uint32_t* hp = (uint32_t*)&hi;
    #pragma unroll
    for (int j = 0; j < 2; ++j) {
        int n = n0 + j * 8;
        #pragma unroll
        for (int g = 0; g < 2; ++g) {
            float v0 = W[(k0 + g * 8) * 128 + n];
            float v1 = W[(k0 + g * 8 + 1) * 128 + n];
            hp[j * 2 + g] = pack_half(v0, v1);
        }
    }
    g_Bpk[t][m][w] = hi;
}

// ---------------- K2: CSR offsets + type-scatter ----------------
__global__ void __launch_bounds__(256) k_off(const int* __restrict__ ntype, int N) {
    __shared__ int sws[8];
    __shared__ int sbase;
    __shared__ int h[3], tb[3];

    int tid = threadIdx.x;
    int lane = tid & 31, w = tid >> 5;
    int i = blockIdx.x * 256 + tid;
    int d = (i < N) ? g_deg[i] : 0;

    if (blockIdx.x == 0 && tid == 0) g_wq = 0;   // for k_attn (launch-ordered)

    int inc = d;
    #pragma unroll
    for (int o = 1; o < 32; o <<= 1) {
        int t = __shfl_up_sync(0xffffffffu, inc, o);
        if (lane >= o) inc += t;
    }
    if (lane == 31) sws[w] = inc;
    if (tid < 3) h[tid] = 0;
    __syncthreads();
    if (tid == 0) {
        int run = 0;
        #pragma unroll
        for (int k = 0; k < 8; ++k) { int t = sws[k]; sws[k] = run; run += t; }
        sbase = atomicAdd(&g_total, run);
    }
    __syncthreads();
    int ex = sbase + sws[w] + inc - d;
    if (i < N) {
        g_offdeg[i] = make_int2(ex, d);
        g_cur2[i] = ex;
    }

    int t = 0, r = 0;
    if (i < N) { t = ntype[i]; r = atomicAdd(&h[t], 1); }
    __syncthreads();
    if (tid < 3 && h[tid]) tb[tid] = atomicAdd(&g_cnt2[tid], h[tid]);
    __syncthreads();
    if (i < N) {
        int base = (t == 0) ? 0 : ((t == 1) ? g_cnt[0] : (g_cnt[0] + g_cnt[1]));
        g_perm[base + tb[t] + r] = i;
    }
}

// ---------------- K3: edge payload scatter (lightweight, no smem) ------------
__global__ void k_escatter(const int* __restrict__ ei, const int* __restrict__ etype,
                           const int* __restrict__ esign, const float* __restrict__ edist,
                           const float* __restrict__ alphap, const float* __restrict__ taup,
                           int E)
{
    int e = blockIdx.x * blockDim.x + threadIdx.x;
    if (e >= E) return;
    int dst = ei[E + e];
    int src = ei[e];
    int et = etype[e];
    int sg = esign[e];
    int sidx = (sg == -1) ? 0 : ((sg == 1) ? 1 : 2);
    float alpha = __ldg(alphap);
    float itau = 1.f / (__ldg(taup) + 1e-9f);
    float phi = alpha * __expf(-edist[e] * itau);
    int pos = atomicAdd(&g_cur2[dst], 1);
    int w = src | ((et * 3 + sidx) << 17) | (et << 22);
    g_epk[pos] = make_int2(w, __float_as_int(phi));
}

// ---------------- K4: tensor-core QKV (R12 shape: 256 thr, 2 blocks/SM) -------
#define SM_STAGE 0
#define SM_B0 33792
#define SM_B1 (33792 + 32768)
#define SM_META (33792 + 65536)
#define SM_TOTAL (SM_META + 1024)

__device__ __forceinline__ void copyB(uint32_t dst, const uint4* src, int tid) {
    #pragma unroll
    for (int i = tid; i < 2048; i += 256) cp16(dst + i * 16, src + i);
    asm volatile("cp.async.commit_group;");
}

__global__ void __launch_bounds__(256, 2) k_qkv_mma(
    const float* __restrict__ x, const int* __restrict__ ntype,
    const float* __restrict__ bq, const float* __restrict__ bk,
    const float* __restrict__ bv, int N)
{
    extern __shared__ __align__(16) unsigned char sm[];
    uint32_t smb = s2u(sm);
    float* raw = (float*)(sm + SM_STAGE);     // 64 rows x 132 floats
    int* sp = (int*)(sm + SM_META);
    int* st = sp + 128;

    int tid = threadIdx.x;
    int wid = tid >> 5;
    int lane = tid & 31;

    int start = blockIdx.x * 128;
    int count = N - start; if (count > 128) count = 128;

    if (tid < count) {
        int pn = g_perm[start + tid];
        sp[tid] = pn;
        st[tid] = ntype[pn];
    }
    __syncthreads();

    int tmin = st[0], tmax = st[count - 1];
    int niter = 3 * (tmax - tmin + 1);

    // prefetch first B while we stage A
    copyB(smb + SM_B0, g_Bpk[tmin][0], tid);

    // A fragments -> registers, 2 chunks of 64 rows through the staging buffer
    uint4 areg[8];
    #pragma unroll
    for (int chunk = 0; chunk < 2; ++chunk) {
        for (int i = tid; i < 2048; i += 256) {
            int row = i >> 5, col = i & 31;
            int gr = chunk * 64 + row;
            float4 v = make_float4(0.f, 0.f, 0.f, 0.f);
            if (gr < count) v = *(const float4*)(x + (size_t)sp[gr] * 128 + col * 4);
            *(float4*)(raw + row * 132 + col * 4) = v;
        }
        __syncthreads();
        if ((wid >> 2) == chunk) {
            int lr = (wid & 3) * 16 + (lane >> 2);
            int q2 = (lane & 3) * 2;
            #pragma unroll
            for (int kt = 0; kt < 8; ++kt) {
                const float* b0 = raw + lr * 132 + kt * 16 + q2;
                float2 f00 = *(const float2*)(b0);
                float2 f10 = *(const float2*)(b0 + 8 * 132);
                float2 f01 = *(const float2*)(b0 + 8);
                float2 f11 = *(const float2*)(b0 + 8 * 132 + 8);
                areg[kt].x = pack_half(f00.x, f00.y);
                areg[kt].y = pack_half(f10.x, f10.y);
                areg[kt].z = pack_half(f01.x, f01.y);
                areg[kt].w = pack_half(f11.x, f11.y);
            }
        }
        __syncthreads();
    }

    for (int it = 0; it < niter; ++it) {
        int t = tmin + it / 3;
        int m = it % 3;
        uint4* Bb = (uint4*)(sm + ((it & 1) ? SM_B1 : SM_B0));

        if (it + 1 < niter) {
            int t2 = tmin + (it + 1) / 3;
            int m2 = (it + 1) % 3;
            copyB(smb + ((it & 1) ? SM_B0 : SM_B1), g_Bpk[t2][m2], tid);
            asm volatile("cp.async.wait_group 1;" ::: "memory");
        } else {
            asm volatile("cp.async.wait_group 0;" ::: "memory");
        }
        __syncthreads();

        float acc[16][4];
        #pragma unroll
        for (int i = 0; i < 16; ++i)
            #pragma unroll
            for (int j = 0; j < 4; ++j) acc[i][j] = 0.f;

        #pragma unroll
        for (int kt = 0; kt < 8; ++kt) {
            uint4 ah = areg[kt];
            #pragma unroll
            for (int np = 0; np < 8; ++np) {
                uint4 bh = Bb[(kt * 8 + np) * 32 + lane];
                mma16816h(acc[2 * np],     ah.x, ah.y, ah.z, ah.w, bh.x, bh.y);
                mma16816h(acc[2 * np + 1], ah.x, ah.y, ah.z, ah.w, bh.z, bh.w);
            }
        }

        // ---- epilogue (all fp16 outputs) ----
        const float* bias = (m == 0 ? bq : (m == 1 ? bk : bv)) + t * 128;
        int row0 = wid * 16 + (lane >> 2);
        int row1 = row0 + 8;
        bool v0ok = (row0 < count) && (st[row0] == t);
        bool v1ok = (row1 < count) && (st[row1] == t);
        int cbase = (lane & 3) * 2;

        __half* d0;
        __half* d1;
        bool interleave;
        if (m == 0) {
            d0 = v0ok ? (g_Qh + (size_t)sp[row0] * 128) : nullptr;
            d1 = v1ok ? (g_Qh + (size_t)sp[row1] * 128) : nullptr;
            interleave = false;
        } else {
            int moff = (m == 2) ? 4 : 0;
            d0 = v0ok ? (g_KVh + (size_t)sp[row0] * 256 + moff) : nullptr;
            d1 = v1ok ? (g_KVh + (size_t)sp[row1] * 256 + moff) : nullptr;
            interleave = true;
        }
        #pragma unroll
        for (int nt = 0; nt < 16; ++nt) {
            int c = nt * 8 + cbase;
            int off = interleave ? (((c >> 2) << 3) + (c & 3)) : c;
            float2 b2 = __ldg((const float2*)(bias + c));
            if (v0ok)
                *(__half2*)(d0 + off) = __floats2half2_rn(acc[nt][0] + b2.x, acc[nt][1] + b2.y);
            if (v1ok)
                *(__half2*)(d1 + off) = __floats2half2_rn(acc[nt][2] + b2.x, acc[nt][3] + b2.y);
        }
        __syncthreads();   // all warps done with Bb before it gets overwritten
    }
}

// ---------------- K5: fused gather-attention + residual + LN ------------------
__global__ void __launch_bounds__(256) k_attn(
    const float* __restrict__ x, const int* __restrict__ ntype,
    const float* __restrict__ rbias,
    const float* __restrict__ skip, const float* __restrict__ gamma,
    const float* __restrict__ beta, float* __restrict__ out, int N)
{
    __shared__ __align__(16) float s_rqk[3072];
    __shared__ __align__(16) float s_rvv[3072];
    __shared__ float s_rb[64];

    int tid = threadIdx.x;
    {
        const uint4* sq = (const uint4*)g_tqk;
        const uint4* sv = (const uint4*)g_tv;
        uint4* dq = (uint4*)s_rqk;
        uint4* dv = (uint4*)s_rvv;
        #pragma unroll 3
        for (int i = tid; i < 768; i += 256) { dq[i] = sq[i]; dv[i] = sv[i]; }
    }
    if (tid < 64) s_rb[tid] = rbias[tid];
    __syncthreads();

    int lane = tid & 31;
    int h = lane >> 2;

    for (;;) {
        int base = 0;
        if (lane == 0) base = atomicAdd(&g_wq, 4);
        base = __shfl_sync(0xffffffffu, base, 0);
        if (base >= N) break;
        int stop = base + 4; if (stop > N) stop = N;

        for (int n = base; n < stop; ++n) {
            float4 q4;
            {
                uint2 qr = *(const uint2*)(g_Qh + (size_t)n * 128 + lane * 4);
                __half2* qh = (__half2*)&qr;
                float2 q01 = __half22float2(qh[0]), q23 = __half22float2(qh[1]);
                q4 = make_float4(q01.x, q01.y, q23.x, q23.y);
            }
            int2 od = g_offdeg[n];
            int start = od.x;
            int deg = od.y;

            float4 oa = make_float4(0.f, 0.f, 0.f, 0.f);
            float z = 0.f;

            int j = 0;
            for (; j + 3 < deg; j += 4) {
                int2 p0 = g_epk[start + j + 0];
                int2 p1 = g_epk[start + j + 1];
                int2 p2 = g_epk[start + j + 2];
                int2 p3 = g_epk[start + j + 3];

                uint4 kv0 = *(const uint4*)(g_KVh + (size_t)(p0.x & 0x1FFFF) * 256 + lane * 8);
                uint4 kv1 = *(const uint4*)(g_KVh + (size_t)(p1.x & 0x1FFFF) * 256 + lane * 8);
                uint4 kv2 = *(const uint4*)(g_KVh + (size_t)(p2.x & 0x1FFFF) * 256 + lane * 8);
                uint4 kv3 = *(const uint4*)(g_KVh + (size_t)(p3.x & 0x1FFFF) * 256 + lane * 8);

                int cb0 = (((p0.x >> 17) & 31) << 7) + lane * 4;
                int cb1 = (((p1.x >> 17) & 31) << 7) + lane * 4;
                int cb2 = (((p2.x >> 17) & 31) << 7) + lane * 4;
                int cb3 = (((p3.x >> 17) & 31) << 7) + lane * 4;

                float4 rk0 = *(float4*)(s_rqk + cb0);
                float4 rk1 = *(float4*)(s_rqk + cb1);
                float4 rk2 = *(float4*)(s_rqk + cb2);
                float4 rk3 = *(float4*)(s_rqk + cb3);

                __half2* h0 = (__half2*)&kv0;
                __half2* h1 = (__half2*)&kv1;
                __half2* h2 = (__half2*)&kv2;
                __half2* h3 = (__half2*)&kv3;

                float2 k0a = __half22float2(h0[0]), k0b = __half22float2(h0[1]);
                float2 k1a = __half22float2(h1[0]), k1b = __half22float2(h1[1]);
                float2 k2a = __half22float2(h2[0]), k2b = __half22float2(h2[1]);
                float2 k3a = __half22float2(h3[0]), k3b = __half22float2(h3[1]);

                float s0 = q4.x * k0a.x * rk0.x + q4.y * k0a.y * rk0.y
                         + q4.z * k0b.x * rk0.z + q4.w * k0b.y * rk0.w;
                float s1 = q4.x * k1a.x * rk1.x + q4.y * k1a.y * rk1.y
                         + q4.z * k1b.x * rk1.z + q4.w * k1b.y * rk1.w;
                float s2 = q4.x * k2a.x * rk2.x + q4.y * k2a.y * rk2.y
                         + q4.z * k2b.x * rk2.z + q4.w * k2b.y * rk2.w;
                float s3 = q4.x * k3a.x * rk3.x + q4.y * k3a.y * rk3.y
                         + q4.z * k3b.x * rk3.z + q4.w * k3b.y * rk3.w;

                s0 += __shfl_xor_sync(0xffffffffu, s0, 1);
                s1 += __shfl_xor_sync(0xffffffffu, s1, 1);
                s2 += __shfl_xor_sync(0xffffffffu, s2, 1);
                s3 += __shfl_xor_sync(0xffffffffu, s3, 1);
                s0 += __shfl_xor_sync(0xffffffffu, s0, 2);
                s1 += __shfl_xor_sync(0xffffffffu, s1, 2);
                s2 += __shfl_xor_sync(0xffffffffu, s2, 2);
                s3 += __shfl_xor_sync(0xffffffffu, s3, 2);

                float e0 = __expf(s0 * 0.25f + s_rb[((p0.x >> 22) & 7) * 8 + h] + __int_as_float(p0.y));
                float e1 = __expf(s1 * 0.25f + s_rb[((p1.x >> 22) & 7) * 8 + h] + __int_as_float(p1.y));
                float e2 = __expf(s2 * 0.25f + s_rb[((p2.x >> 22) & 7) * 8 + h] + __int_as_float(p2.y));
                float e3 = __expf(s3 * 0.25f + s_rb[((p3.x >> 22) & 7) * 8 + h] + __int_as_float(p3.y));
                z += (e0 + e1) + (e2 + e3);

                float4 rv0 = *(float4*)(s_rvv + cb0);
                float4 rv1 = *(float4*)(s_rvv + cb1);
                float4 rv2 = *(float4*)(s_rvv + cb2);
                float4 rv3 = *(float4*)(s_rvv + cb3);

                float2 v0a = __half22float2(h0[2]), v0b = __half22float2(h0[3]);
                float2 v1a = __half22float2(h1[2]), v1b = __half22float2(h1[3]);
                float2 v2a = __half22float2(h2[2]), v2b = __half22float2(h2[3]);
                float2 v3a = __half22float2(h3[2]), v3b = __half22float2(h3[3]);

                oa.x += v0a.x * rv0.x * e0 + v1a.x * rv1.x * e1
                      + v2a.x * rv2.x * e2 + v3a.x * rv3.x * e3;
                oa.y += v0a.y * rv0.y * e0 + v1a.y * rv1.y * e1
                      + v2a.y * rv2.y * e2 + v3a.y * rv3.y * e3;
                oa.z += v0b.x * rv0.z * e0 + v1b.x * rv1.z * e1
                      + v2b.x * rv2.z * e2 + v3b.x * rv3.z * e3;
                oa.w += v0b.y * rv0.w * e0 + v1b.y * rv1.w * e1
                      + v2b.y * rv2.w * e2 + v3b.y * rv3.w * e3;
            }
            for (; j < deg; ++j) {
                int2 p = g_epk[start + j];
                uint4 kv = *(const uint4*)(g_KVh + (size_t)(p.x & 0x1FFFF) * 256 + lane * 8);
                int cb = (((p.x >> 17) & 31) << 7) + lane * 4;
                float4 rk4 = *(float4*)(s_rqk + cb);
                float4 rv4 = *(float4*)(s_rvv + cb);

                __half2* hh = (__half2*)&kv;
                float2 k01 = __half22float2(hh[0]), k23 = __half22float2(hh[1]);
                float2 v01 = __half22float2(hh[2]), v23 = __half22float2(hh[3]);

                float sc = q4.x * k01.x * rk4.x + q4.y * k01.y * rk4.y
                         + q4.z * k23.x * rk4.z + q4.w * k23.y * rk4.w;
                sc += __shfl_xor_sync(0xffffffffu, sc, 1);
                sc += __shfl_xor_sync(0xffffffffu, sc, 2);

                float es = __expf(sc * 0.25f + s_rb[((p.x >> 22) & 7) * 8 + h] + __int_as_float(p.y));
                z += es;
                oa.x += v01.x * rv4.x * es;
                oa.y += v01.y * rv4.y * es;
                oa.z += v23.x * rv4.z * es;
                oa.w += v23.y * rv4.w * es;
            }

            int t = ntype[n];
            float a = 1.f / (1.f + __expf(-__ldg(skip + t)));
            float b = 1.f - a;
            float r = a / (z + 1e-9f);

            float4 xi = *(const float4*)(x + (size_t)n * 128 + lane * 4);
            float4 xv;
            xv.x = oa.x * r + b * xi.x;
            xv.y = oa.y * r + b * xi.y;
            xv.z = oa.z * r + b * xi.z;
            xv.w = oa.w * r + b * xi.w;

            float s = xv.x + xv.y + xv.z + xv.w;
            #pragma unroll
            for (int o = 16; o; o >>= 1) s += __shfl_xor_sync(0xffffffffu, s, o);
            float mu = s * (1.f / 128.f);

            float dx0 = xv.x - mu, dx1 = xv.y - mu, dx2 = xv.z - mu, dx3 = xv.w - mu;
            float vs = dx0 * dx0 + dx1 * dx1 + dx2 * dx2 + dx3 * dx3;
            #pragma unroll
            for (int o = 16; o; o >>= 1) vs += __shfl_xor_sync(0xffffffffu, vs, o);
            float rs = rsqrtf(vs * (1.f / 128.f) + 1e-5f);

            float4 g4 = *(const float4*)(gamma + t * 128 + lane * 4);
            float4 be4 = *(const float4*)(beta + t * 128 + lane * 4);

            float4 y;
            y.x = dx0 * rs * g4.x + be4.x;
            y.y = dx1 * rs * g4.y + be4.y;
            y.z = dx2 * rs * g4.z + be4.z;
            y.w = dx3 * rs * g4.w + be4.w;

            *(float4*)(out + (size_t)n * 128 + lane * 4) = y;
        }
    }

    // tail: re-zero build state for the next graph replay
    int gi = blockIdx.x * blockDim.x + tid;
    if (gi < N) g_deg[gi] = 0;
    if (gi < 3) g_cnt[gi] = 0;
}

// ---------------- launch ----------------
extern "C" void kernel_launch(void* const* d_in, const int* in_sizes, int n_in,
                              void* d_out, int out_size)
{
    const float* node_inp   = (const float*)d_in[0];
    const int*   node_type  = (const int*)d_in[1];
    const int*   edge_index = (const int*)d_in[2];
    const int*   edge_type  = (const int*)d_in[3];
    const int*   edge_sign  = (const int*)d_in[4];
    const float* edge_dist  = (const float*)d_in[5];
    const float* Wq = (const float*)d_in[6];
    const float* bq = (const float*)d_in[7];
    const float* Wk = (const float*)d_in[8];
    const float* bk = (const float*)d_in[9];
    const float* Wv = (const float*)d_in[10];
    const float* bv = (const float*)d_in[11];
    const float* rel_q   = (const float*)d_in[12];
    const float* rel_k   = (const float*)d_in[13];
    const float* rel_v   = (const float*)d_in[14];
    const float* rel_b   = (const float*)d_in[15];
    const float* skf     = (const float*)d_in[16];
    const float* svf     = (const float*)d_in[17];
    const float* skn     = (const float*)d_in[18];
    const float* svn     = (const float*)d_in[19];
    const float* d_alpha = (const float*)d_in[20];
    const float* d_tau   = (const float*)d_in[21];
    const float* skip    = (const float*)d_in[22];
    const float* ln_g    = (const float*)d_in[23];
    const float* ln_b    = (const float*)d_in[24];

    int N = in_sizes[1];
    int E = in_sizes[3];

    float* out = (float*)d_out;

    cudaFuncSetAttribute(k_qkv_mma, cudaFuncAttributeMaxDynamicSharedMemorySize, SM_TOTAL);

    int nb = (N + 255) / 256;
    int eb = (E + 255) / 256;
    int qb = (N + 127) / 128;

    k_histpack<<<eb + 72, 256>>>(node_type, edge_index, Wq, Wk, Wv,
                                 rel_q, rel_k, rel_v, skf, svf, skn, svn, N, E, eb);
    k_off<<<nb, 256>>>(node_type, N);
    k_escatter<<<eb, 256>>>(edge_index, edge_type, edge_sign, edge_dist,
                            d_alpha, d_tau, E);
    k_qkv_mma<<<qb, 256, SM_TOTAL>>>(node_inp, node_type, bq, bk, bv, N);
    k_attn<<<740, 256>>>(node_inp, node_type, rel_b, skip, ln_g, ln_b, out, N);
}